// round 1
// baseline (speedup 1.0000x reference)
#include <cuda_runtime.h>

#define N_NODES   50000
#define N_EDGES   800000
#define IN_DIM    64
#define HD        64       // NUM_HEADS * OUT_DIM
#define NUM_HEADS 4
#define OUT_DIM   16
#define NEG_SLOPE 0.2f

// Scratch (allocation-free rule: __device__ globals)
__device__ __align__(16) float g_feat[N_NODES * HD];
__device__ __align__(16) float g_el[N_NODES * NUM_HEADS];
__device__ __align__(16) float g_er[N_NODES * NUM_HEADS];
__device__ int g_idx64;

// ---------------------------------------------------------------------------
// Detect whether src/dst are int64 or int32 (reference says int64; default
// JAX demotes to int32). int64 little-endian with values < 2^31 has every
// odd int32 word == 0.
// ---------------------------------------------------------------------------
__global__ void detect_idx_kernel(const int* __restrict__ p) {
    if (threadIdx.x == 0) {
        int zeros = 0;
        #pragma unroll 1
        for (int i = 0; i < 256; i++) zeros += (p[2 * i + 1] == 0);
        g_idx64 = (zeros > 200) ? 1 : 0;
    }
}

__device__ __forceinline__ int ld_idx(const void* p, int i, int is64) {
    if (is64) return (int)((const long long*)p)[i];
    return ((const int*)p)[i];
}

// ---------------------------------------------------------------------------
// Fused: feat = h@W_fc (to g_feat), out = h@W_res (resval, initializes d_out),
// el/er per (node, head).
// Warp per node. Weights staged in shared: Ws[k][c], c<64 -> W_fc, c>=64 -> W_res.
// ---------------------------------------------------------------------------
__global__ void __launch_bounds__(256) fc_kernel(
    const float* __restrict__ h,
    const float* __restrict__ Wfc,
    const float* __restrict__ Wres,
    const float* __restrict__ attn_l,
    const float* __restrict__ attn_r,
    float* __restrict__ out)
{
    __shared__ float Ws[64][128];
    int tid = threadIdx.x;
    for (int i = tid; i < 64 * 64; i += blockDim.x) {
        int k = i >> 6, c = i & 63;
        Ws[k][c]      = Wfc[i];
        Ws[k][64 + c] = Wres[i];
    }
    __syncthreads();

    int lane = tid & 31;
    int warp = tid >> 5;
    int node = blockIdx.x * (blockDim.x >> 5) + warp;
    if (node >= N_NODES) return;

    float h0 = h[node * 64 + lane];
    float h1 = h[node * 64 + 32 + lane];

    float a0 = 0.f, a1 = 0.f, a2 = 0.f, a3 = 0.f;
    #pragma unroll
    for (int k = 0; k < 64; k++) {
        float hk = (k < 32) ? __shfl_sync(0xffffffffu, h0, k)
                            : __shfl_sync(0xffffffffu, h1, k - 32);
        a0 = fmaf(hk, Ws[k][lane],      a0);   // W_fc col lane
        a1 = fmaf(hk, Ws[k][lane + 32], a1);   // W_fc col lane+32
        a2 = fmaf(hk, Ws[k][lane + 64], a2);   // W_res col lane
        a3 = fmaf(hk, Ws[k][lane + 96], a3);   // W_res col lane+32
    }

    g_feat[node * 64 + lane]      = a0;
    g_feat[node * 64 + 32 + lane] = a1;
    out[node * 64 + lane]         = a2;   // resval -> also initializes output
    out[node * 64 + 32 + lane]    = a3;

    // el/er: col c belongs to head c/16. acc0 -> heads {0,1}, acc1 -> heads {2,3}
    float al0 = attn_l[lane], al1 = attn_l[32 + lane];
    float ar0 = attn_r[lane], ar1 = attn_r[32 + lane];
    float pl0 = a0 * al0, pl1 = a1 * al1;
    float pr0 = a0 * ar0, pr1 = a1 * ar1;
    #pragma unroll
    for (int o = 8; o >= 1; o >>= 1) {
        pl0 += __shfl_down_sync(0xffffffffu, pl0, o, 16);
        pl1 += __shfl_down_sync(0xffffffffu, pl1, o, 16);
        pr0 += __shfl_down_sync(0xffffffffu, pr0, o, 16);
        pr1 += __shfl_down_sync(0xffffffffu, pr1, o, 16);
    }
    if ((lane & 15) == 0) {
        int hh = lane >> 4;  // 0 or 1
        g_el[node * 4 + hh]     = pl0;
        g_el[node * 4 + 2 + hh] = pl1;
        g_er[node * 4 + hh]     = pr0;
        g_er[node * 4 + 2 + hh] = pr1;
    }
}

// ---------------------------------------------------------------------------
// Edge scatter with fused leaky-relu + head-softmax.
// 16 lanes per edge; lane j handles feat[src][4j..4j+3] (head = j/4).
// Vector reduction red.global.add.v4.f32 -> 4x fewer L2 atomic ops.
// ---------------------------------------------------------------------------
__global__ void __launch_bounds__(256) scatter_kernel(
    const void* __restrict__ src,
    const void* __restrict__ dst,
    float* __restrict__ out)
{
    long long t = (long long)blockIdx.x * blockDim.x + threadIdx.x;
    int e = (int)(t >> 4);
    if (e >= N_EDGES) return;
    int j = (int)(t & 15);

    int is64 = g_idx64;
    int s = ld_idx(src, e, is64);
    int d = ld_idx(dst, e, is64);

    // all 16 lanes of the edge load the same 16B -> L1 broadcast
    float4 el = *(const float4*)&g_el[s * 4];
    float4 er = *(const float4*)&g_er[d * 4];

    float e0 = el.x + er.x, e1 = el.y + er.y;
    float e2 = el.z + er.z, e3 = el.w + er.w;
    e0 = (e0 > 0.f) ? e0 : NEG_SLOPE * e0;
    e1 = (e1 > 0.f) ? e1 : NEG_SLOPE * e1;
    e2 = (e2 > 0.f) ? e2 : NEG_SLOPE * e2;
    e3 = (e3 > 0.f) ? e3 : NEG_SLOPE * e3;

    float m = fmaxf(fmaxf(e0, e1), fmaxf(e2, e3));
    float x0 = __expf(e0 - m), x1 = __expf(e1 - m);
    float x2 = __expf(e2 - m), x3 = __expf(e3 - m);
    float inv = 1.0f / (x0 + x1 + x2 + x3);

    int hh = j >> 2;
    float a = ((hh == 0) ? x0 : (hh == 1) ? x1 : (hh == 2) ? x2 : x3) * inv;

    float4 f = *(const float4*)&g_feat[s * 64 + j * 4];
    float4 v = make_float4(f.x * a, f.y * a, f.z * a, f.w * a);

    float* addr = out + (long long)d * 64 + j * 4;
    asm volatile("red.global.add.v4.f32 [%0], {%1,%2,%3,%4};"
                 :: "l"(addr), "f"(v.x), "f"(v.y), "f"(v.z), "f"(v.w)
                 : "memory");
}

// ---------------------------------------------------------------------------
extern "C" void kernel_launch(void* const* d_in, const int* in_sizes, int n_in,
                              void* d_out, int out_size) {
    const float* h    = (const float*)d_in[0];
    const void*  src  = d_in[1];
    const void*  dst  = d_in[2];
    const float* Wfc  = (const float*)d_in[3];
    const float* al   = (const float*)d_in[4];
    const float* ar   = (const float*)d_in[5];
    const float* Wres = (const float*)d_in[6];
    float* out = (float*)d_out;

    detect_idx_kernel<<<1, 32>>>((const int*)src);

    int nodes_per_block = 256 / 32;
    int fc_blocks = (N_NODES + nodes_per_block - 1) / nodes_per_block;
    fc_kernel<<<fc_blocks, 256>>>(h, Wfc, Wres, al, ar, out);

    long long threads = (long long)N_EDGES * 16;
    int sc_blocks = (int)((threads + 255) / 256);
    scatter_kernel<<<sc_blocks, 256>>>(src, dst, out);
}

// round 2
// speedup vs baseline: 1.3294x; 1.3294x over previous
#include <cuda_runtime.h>

#define N_NODES   50000
#define N_EDGES   800000
#define IN_DIM    64
#define HD        64       // NUM_HEADS * OUT_DIM
#define NUM_HEADS 4
#define OUT_DIM   16
#define NEG_SLOPE 0.2f

// Scratch (allocation-free rule: __device__ globals)
__device__ __align__(16) float g_feat[N_NODES * HD];
__device__ __align__(16) float g_el[N_NODES * NUM_HEADS];
__device__ __align__(16) float g_er[N_NODES * NUM_HEADS];
__device__ int g_idx64;

__device__ __forceinline__ int ld_idx(const void* p, int i, int is64) {
    if (is64) return (int)((const long long*)p)[i];
    return ((const int*)p)[i];
}

// ---------------------------------------------------------------------------
// Fused: feat = h@W_fc (to g_feat), out = h@W_res (resval, initializes d_out),
// el/er per (node, head). Warp per node; weights interleaved as float4 in smem
// (one LDS.128 per k-step instead of 4 scalar LDS).
// Block 0 / warp 0 additionally detects src index width (int64 vs int32):
// int64 little-endian with values < 2^31 has every odd int32 word == 0.
// ---------------------------------------------------------------------------
__global__ void __launch_bounds__(256) fc_kernel(
    const float* __restrict__ h,
    const float* __restrict__ Wfc,
    const float* __restrict__ Wres,
    const float* __restrict__ attn_l,
    const float* __restrict__ attn_r,
    const int*   __restrict__ src_raw,
    float* __restrict__ out)
{
    int tid = threadIdx.x;

    // --- index-width detection (1 load round, 32 lanes, ballot) ---
    if (blockIdx.x == 0 && tid < 32) {
        int w = src_raw[2 * tid + 1];                 // odd 32-bit words
        unsigned bal = __ballot_sync(0xffffffffu, w == 0);
        if (tid == 0) g_idx64 = (__popc(bal) >= 30) ? 1 : 0;
    }

    // --- stage interleaved weights: Ws[k][c] = {Wfc[k][c], Wfc[k][c+32],
    //                                            Wres[k][c], Wres[k][c+32]} ---
    __shared__ float4 Ws[64][32];
    for (int i = tid; i < 64 * 32; i += 256) {
        int k = i >> 5, c = i & 31;
        Ws[k][c] = make_float4(Wfc[k * 64 + c], Wfc[k * 64 + 32 + c],
                               Wres[k * 64 + c], Wres[k * 64 + 32 + c]);
    }
    __syncthreads();

    int lane = tid & 31;
    int warp = tid >> 5;
    int node = blockIdx.x * 8 + warp;
    if (node >= N_NODES) return;

    float h0 = h[node * 64 + lane];
    float h1 = h[node * 64 + 32 + lane];

    float a0 = 0.f, a1 = 0.f, a2 = 0.f, a3 = 0.f;
    #pragma unroll
    for (int k = 0; k < 64; k++) {
        float hk = (k < 32) ? __shfl_sync(0xffffffffu, h0, k)
                            : __shfl_sync(0xffffffffu, h1, k - 32);
        float4 w = Ws[k][lane];
        a0 = fmaf(hk, w.x, a0);   // W_fc  col lane
        a1 = fmaf(hk, w.y, a1);   // W_fc  col lane+32
        a2 = fmaf(hk, w.z, a2);   // W_res col lane
        a3 = fmaf(hk, w.w, a3);   // W_res col lane+32
    }

    g_feat[node * 64 + lane]      = a0;
    g_feat[node * 64 + 32 + lane] = a1;
    out[node * 64 + lane]         = a2;   // resval -> also initializes output
    out[node * 64 + 32 + lane]    = a3;

    // el/er: col c belongs to head c/16. a0 -> heads {0,1}, a1 -> heads {2,3}
    float al0 = attn_l[lane], al1 = attn_l[32 + lane];
    float ar0 = attn_r[lane], ar1 = attn_r[32 + lane];
    float pl0 = a0 * al0, pl1 = a1 * al1;
    float pr0 = a0 * ar0, pr1 = a1 * ar1;
    #pragma unroll
    for (int o = 8; o >= 1; o >>= 1) {
        pl0 += __shfl_down_sync(0xffffffffu, pl0, o, 16);
        pl1 += __shfl_down_sync(0xffffffffu, pl1, o, 16);
        pr0 += __shfl_down_sync(0xffffffffu, pr0, o, 16);
        pr1 += __shfl_down_sync(0xffffffffu, pr1, o, 16);
    }
    if ((lane & 15) == 0) {
        int hh = lane >> 4;  // 0 or 1
        g_el[node * 4 + hh]     = pl0;
        g_el[node * 4 + 2 + hh] = pl1;
        g_er[node * 4 + hh]     = pr0;
        g_er[node * 4 + 2 + hh] = pr1;
    }
}

// ---------------------------------------------------------------------------
// Edge scatter with fused leaky-relu + head-softmax.
// 16 lanes per edge; lane j owns head (j&3), dim group (j>>2):
//   columns (j&3)*16 + (j>>2)*4 .. +3.
// Each lane computes exactly ONE expf; max+sum via 4-lane butterfly shuffles.
// red.global.add.v4.f32 -> 4x fewer L2 atomic ops vs scalar atomics.
// ---------------------------------------------------------------------------
__global__ void __launch_bounds__(256) scatter_kernel(
    const void* __restrict__ src,
    const void* __restrict__ dst,
    float* __restrict__ out)
{
    int t = blockIdx.x * 256 + threadIdx.x;          // 12.8M < 2^31
    int e = t >> 4;
    if (e >= N_EDGES) return;
    int j = t & 15;
    int hh = j & 3;            // head this lane computes & consumes
    int g  = j >> 2;           // dim group within head

    int is64 = g_idx64;
    int s = ld_idx(src, e, is64);
    int d = ld_idx(dst, e, is64);

    float ev = g_el[s * 4 + hh] + g_er[d * 4 + hh];
    ev = (ev > 0.f) ? ev : NEG_SLOPE * ev;

    // softmax over the 4 heads: lanes {4g..4g+3} hold heads 0..3
    float m = ev;
    m = fmaxf(m, __shfl_xor_sync(0xffffffffu, m, 1));
    m = fmaxf(m, __shfl_xor_sync(0xffffffffu, m, 2));
    float x = __expf(ev - m);
    float ssum = x;
    ssum += __shfl_xor_sync(0xffffffffu, ssum, 1);
    ssum += __shfl_xor_sync(0xffffffffu, ssum, 2);
    float a = __fdividef(x, ssum);

    int col = hh * 16 + g * 4;
    float4 f = *(const float4*)&g_feat[s * 64 + col];
    float4 v = make_float4(f.x * a, f.y * a, f.z * a, f.w * a);

    float* addr = out + (long long)d * 64 + col;
    asm volatile("red.global.add.v4.f32 [%0], {%1,%2,%3,%4};"
                 :: "l"(addr), "f"(v.x), "f"(v.y), "f"(v.z), "f"(v.w)
                 : "memory");
}

// ---------------------------------------------------------------------------
extern "C" void kernel_launch(void* const* d_in, const int* in_sizes, int n_in,
                              void* d_out, int out_size) {
    const float* h    = (const float*)d_in[0];
    const void*  src  = d_in[1];
    const void*  dst  = d_in[2];
    const float* Wfc  = (const float*)d_in[3];
    const float* al   = (const float*)d_in[4];
    const float* ar   = (const float*)d_in[5];
    const float* Wres = (const float*)d_in[6];
    float* out = (float*)d_out;

    int fc_blocks = (N_NODES + 7) / 8;
    fc_kernel<<<fc_blocks, 256>>>(h, Wfc, Wres, al, ar, (const int*)src, out);

    long long threads = (long long)N_EDGES * 16;
    int sc_blocks = (int)((threads + 255) / 256);
    scatter_kernel<<<sc_blocks, 256>>>(src, dst, out);
}

// round 3
// speedup vs baseline: 1.8554x; 1.3957x over previous
#include <cuda_runtime.h>

#define N_NODES   50000
#define N_EDGES   800000
#define IN_DIM    64
#define HD        64       // NUM_HEADS * OUT_DIM
#define NUM_HEADS 4
#define OUT_DIM   16
#define NEG_SLOPE 0.2f

// Scratch (allocation-free rule: __device__ globals)
__device__ __align__(16) float g_feat[N_NODES * HD];
__device__ __align__(16) float g_el[N_NODES * NUM_HEADS];
__device__ __align__(16) float g_er[N_NODES * NUM_HEADS];
__device__ int g_idx64;

__device__ __forceinline__ int ld_idx(const void* p, int i, int is64) {
    if (is64) return (int)((const long long*)p)[i];
    return ((const int*)p)[i];
}

// ---------------------------------------------------------------------------
// Register-tiled dual GEMM: [64 nodes] x [128 cols] per block, cols 0..63 =
// W_fc -> g_feat, cols 64..127 = W_res -> out (resval; initializes d_out).
// Thread microtile: 4 nodes x 8 cols -> 32 FFMA per k-step vs 6 LDS.
// FFMA-pipe bound (~24us) instead of smem-crossbar bound (~48us).
// Block 0 also detects index width (int64 vs int32) for src/dst.
// ---------------------------------------------------------------------------
__global__ void __launch_bounds__(256) fc_kernel(
    const float* __restrict__ h,
    const float* __restrict__ Wfc,
    const float* __restrict__ Wres,
    const int*   __restrict__ src_raw,
    float* __restrict__ out)
{
    __shared__ float  hs[64][64];     // [node_local][k]   16KB
    __shared__ float4 ws[64][32];     // [k][col_quad] q<16: Wfc, q>=16: Wres  32KB

    int tid  = threadIdx.x;
    int base = blockIdx.x * 64;

    // --- index-width detection (int64 LE with values < 2^31: odd words == 0)
    if (blockIdx.x == 0 && tid < 32) {
        int w = src_raw[2 * tid + 1];
        unsigned bal = __ballot_sync(0xffffffffu, w == 0);
        if (tid == 0) g_idx64 = (__popc(bal) >= 30) ? 1 : 0;
    }

    // --- stage weights (2048 float4, coalesced) ---
    const float4* Wfc4  = (const float4*)Wfc;
    const float4* Wres4 = (const float4*)Wres;
    #pragma unroll
    for (int i = tid; i < 2048; i += 256) {
        int k = i >> 5, q = i & 31;
        ws[k][q] = (q < 16) ? Wfc4[k * 16 + q] : Wres4[k * 16 + (q - 16)];
    }
    // --- stage h tile (1024 float4, coalesced, row-major: no transpose) ---
    const float4* h4 = (const float4*)h;
    #pragma unroll
    for (int i = tid; i < 1024; i += 256) {
        int nl = i >> 4, kq = i & 15;
        int node = base + nl;
        float4 v = (node < N_NODES) ? h4[node * 16 + kq]
                                    : make_float4(0.f, 0.f, 0.f, 0.f);
        *(float4*)&hs[nl][kq * 4] = v;
    }
    __syncthreads();

    int cx = tid & 15;   // cols cx*8 .. cx*8+7
    int ny = tid >> 4;   // nodes ny*4 .. ny*4+3

    float acc[4][8];
    #pragma unroll
    for (int i = 0; i < 4; i++)
        #pragma unroll
        for (int j = 0; j < 8; j++) acc[i][j] = 0.f;

    #pragma unroll 8
    for (int k = 0; k < 64; k++) {
        float4 w0 = ws[k][2 * cx];
        float4 w1 = ws[k][2 * cx + 1];
        float hv[4];
        #pragma unroll
        for (int i = 0; i < 4; i++) hv[i] = hs[ny * 4 + i][k];
        #pragma unroll
        for (int i = 0; i < 4; i++) {
            acc[i][0] = fmaf(hv[i], w0.x, acc[i][0]);
            acc[i][1] = fmaf(hv[i], w0.y, acc[i][1]);
            acc[i][2] = fmaf(hv[i], w0.z, acc[i][2]);
            acc[i][3] = fmaf(hv[i], w0.w, acc[i][3]);
            acc[i][4] = fmaf(hv[i], w1.x, acc[i][4]);
            acc[i][5] = fmaf(hv[i], w1.y, acc[i][5]);
            acc[i][6] = fmaf(hv[i], w1.z, acc[i][6]);
            acc[i][7] = fmaf(hv[i], w1.w, acc[i][7]);
        }
    }

    #pragma unroll
    for (int i = 0; i < 4; i++) {
        int node = base + ny * 4 + i;
        if (node >= N_NODES) break;
        float* dstp = (cx < 8) ? &g_feat[node * 64 + cx * 8]
                               : &out[node * 64 + (cx - 8) * 8];
        *(float4*)&dstp[0] = make_float4(acc[i][0], acc[i][1], acc[i][2], acc[i][3]);
        *(float4*)&dstp[4] = make_float4(acc[i][4], acc[i][5], acc[i][6], acc[i][7]);
    }
}

// ---------------------------------------------------------------------------
// el/er: per (node, head) dot of feat with attn_l / attn_r.
// 16 lanes per node (2 nodes per warp); lane q owns cols q*4..q*4+3
// (head q>>2); 4-lane butterfly reduce; lanes q%4==0 write.
// ---------------------------------------------------------------------------
__global__ void __launch_bounds__(256) eler_kernel(
    const float* __restrict__ attn_l,
    const float* __restrict__ attn_r)
{
    int tid  = threadIdx.x;
    int lane = tid & 31;
    int warp = tid >> 5;
    int n = blockIdx.x * 16 + warp * 2 + (lane >> 4);   // N_NODES = 3125*16
    int q = lane & 15;

    float4 f  = *(const float4*)&g_feat[n * 64 + q * 4];
    float4 al = __ldg(&((const float4*)attn_l)[q]);
    float4 ar = __ldg(&((const float4*)attn_r)[q]);

    float pl = f.x * al.x + f.y * al.y + f.z * al.z + f.w * al.w;
    float pr = f.x * ar.x + f.y * ar.y + f.z * ar.z + f.w * ar.w;
    pl += __shfl_xor_sync(0xffffffffu, pl, 1);
    pl += __shfl_xor_sync(0xffffffffu, pl, 2);
    pr += __shfl_xor_sync(0xffffffffu, pr, 1);
    pr += __shfl_xor_sync(0xffffffffu, pr, 2);

    if ((lane & 3) == 0) {
        g_el[n * 4 + (q >> 2)] = pl;
        g_er[n * 4 + (q >> 2)] = pr;
    }
}

// ---------------------------------------------------------------------------
// Edge scatter with fused leaky-relu + head-softmax (unchanged from R2).
// 16 lanes per edge; lane j owns head (j&3), dim group (j>>2).
// One expf per lane; 4-lane butterfly for max+sum; red.global.add.v4.f32.
// ---------------------------------------------------------------------------
__global__ void __launch_bounds__(256) scatter_kernel(
    const void* __restrict__ src,
    const void* __restrict__ dst,
    float* __restrict__ out)
{
    int t = blockIdx.x * 256 + threadIdx.x;
    int e = t >> 4;
    if (e >= N_EDGES) return;
    int j  = t & 15;
    int hh = j & 3;
    int g  = j >> 2;

    int is64 = g_idx64;
    int s = ld_idx(src, e, is64);
    int d = ld_idx(dst, e, is64);

    float ev = g_el[s * 4 + hh] + g_er[d * 4 + hh];
    ev = (ev > 0.f) ? ev : NEG_SLOPE * ev;

    float m = ev;
    m = fmaxf(m, __shfl_xor_sync(0xffffffffu, m, 1));
    m = fmaxf(m, __shfl_xor_sync(0xffffffffu, m, 2));
    float x = __expf(ev - m);
    float ssum = x;
    ssum += __shfl_xor_sync(0xffffffffu, ssum, 1);
    ssum += __shfl_xor_sync(0xffffffffu, ssum, 2);
    float a = __fdividef(x, ssum);

    int col = hh * 16 + g * 4;
    float4 f = *(const float4*)&g_feat[s * 64 + col];
    float4 v = make_float4(f.x * a, f.y * a, f.z * a, f.w * a);

    float* addr = out + (long long)d * 64 + col;
    asm volatile("red.global.add.v4.f32 [%0], {%1,%2,%3,%4};"
                 :: "l"(addr), "f"(v.x), "f"(v.y), "f"(v.z), "f"(v.w)
                 : "memory");
}

// ---------------------------------------------------------------------------
extern "C" void kernel_launch(void* const* d_in, const int* in_sizes, int n_in,
                              void* d_out, int out_size) {
    const float* h    = (const float*)d_in[0];
    const void*  src  = d_in[1];
    const void*  dst  = d_in[2];
    const float* Wfc  = (const float*)d_in[3];
    const float* al   = (const float*)d_in[4];
    const float* ar   = (const float*)d_in[5];
    const float* Wres = (const float*)d_in[6];
    float* out = (float*)d_out;

    int fc_blocks = (N_NODES + 63) / 64;                 // 782
    fc_kernel<<<fc_blocks, 256>>>(h, Wfc, Wres, (const int*)src, out);

    eler_kernel<<<N_NODES / 16, 256>>>(al, ar);          // 3125 blocks

    long long threads = (long long)N_EDGES * 16;
    int sc_blocks = (int)((threads + 255) / 256);
    scatter_kernel<<<sc_blocks, 256>>>(src, dst, out);
}

// round 8
// speedup vs baseline: 1.8561x; 1.0004x over previous
#include <cuda_runtime.h>

#define N_NODES   50000
#define N_EDGES   800000
#define IN_DIM    64
#define HD        64       // NUM_HEADS * OUT_DIM
#define NUM_HEADS 4
#define OUT_DIM   16
#define NEG_SLOPE 0.2f

typedef unsigned long long u64;

// Scratch (allocation-free rule: __device__ globals)
__device__ __align__(16) float g_feat[N_NODES * HD];
__device__ __align__(16) float g_el[N_NODES * NUM_HEADS];
__device__ __align__(16) float g_er[N_NODES * NUM_HEADS];
__device__ int g_idx64;

__device__ __forceinline__ int ld_idx(const void* p, int i, int is64) {
    if (is64) return (int)((const long long*)p)[i];
    return ((const int*)p)[i];
}

// Packed fp32x2 helpers (sm_103a FFMA2 — only reachable via PTX)
__device__ __forceinline__ u64 pack2(float x) {
    u64 r; asm("mov.b64 %0, {%1, %1};" : "=l"(r) : "f"(x)); return r;
}
__device__ __forceinline__ void ffma2(u64& d, u64 a, u64 b) {
    asm("fma.rn.f32x2 %0, %1, %2, %0;" : "+l"(d) : "l"(a), "l"(b));
}
__device__ __forceinline__ float unpack_sum(u64 v) {
    float lo, hi; asm("mov.b64 {%0, %1}, %2;" : "=f"(lo), "=f"(hi) : "l"(v));
    return lo + hi;
}

// ---------------------------------------------------------------------------
// Register-tiled dual GEMM with packed FFMA2, fused el/er epilogue.
// Block: 64 nodes x 128 cols (cols 0..63 = W_fc -> g_feat, 64..127 = W_res ->
// out). Thread: 4 nodes x 8 cols as 16 packed f32x2 accumulators.
// Per k-step: 2x LDS.128 (w pairs, free packing) + 4x broadcast LDS.32 (h,
// conflict-free via 68-float row pad) + 4 packs + 16 FFMA2.
// Epilogue: per-head dots of feat with attn_l/attn_r in f32x2. ALL lanes
// compute + shuffle (full-warp mask safety); only cx<8, even-cx lanes write.
// Block 0 also detects index width (int64 vs int32) for src/dst.
// ---------------------------------------------------------------------------
__global__ void __launch_bounds__(256) fc_kernel(
    const float* __restrict__ h,
    const float* __restrict__ Wfc,
    const float* __restrict__ Wres,
    const float* __restrict__ attn_l,
    const float* __restrict__ attn_r,
    const int*   __restrict__ src_raw,
    float* __restrict__ out)
{
    __shared__ float  hs[64][68];     // [node_local][k], padded: bank-free loads
    __shared__ float4 ws[64][32];     // [k][col_quad] q<16: Wfc, q>=16: Wres

    int tid  = threadIdx.x;
    int base = blockIdx.x * 64;

    // --- index-width detection (int64 LE with values < 2^31: odd words == 0)
    if (blockIdx.x == 0 && tid < 32) {
        int w = src_raw[2 * tid + 1];
        unsigned bal = __ballot_sync(0xffffffffu, w == 0);
        if (tid == 0) g_idx64 = (__popc(bal) >= 30) ? 1 : 0;
    }

    // --- stage weights (coalesced float4) ---
    const float4* Wfc4  = (const float4*)Wfc;
    const float4* Wres4 = (const float4*)Wres;
    #pragma unroll
    for (int i = tid; i < 2048; i += 256) {
        int k = i >> 5, q = i & 31;
        ws[k][q] = (q < 16) ? Wfc4[k * 16 + q] : Wres4[k * 16 + (q - 16)];
    }
    // --- stage h tile (coalesced float4 in, 4-phase STS) ---
    const float4* h4 = (const float4*)h;
    #pragma unroll
    for (int i = tid; i < 1024; i += 256) {
        int nl = i >> 4, kq = i & 15;
        int node = base + nl;
        float4 v = (node < N_NODES) ? h4[node * 16 + kq]
                                    : make_float4(0.f, 0.f, 0.f, 0.f);
        *(float4*)&hs[nl][kq * 4] = v;
    }
    __syncthreads();

    int cx = tid & 15;   // cols cx*8 .. cx*8+7
    int ny = tid >> 4;   // nodes ny*4 .. ny*4+3

    u64 acc[4][4];       // [node][col_pair], pair p = cols (8cx+2p, 8cx+2p+1)
    #pragma unroll
    for (int i = 0; i < 4; i++)
        #pragma unroll
        for (int p = 0; p < 4; p++) acc[i][p] = 0ull;

    #pragma unroll 8
    for (int k = 0; k < 64; k++) {
        ulonglong2 wa = *(const ulonglong2*)&ws[k][2 * cx];      // pairs 0,1
        ulonglong2 wb = *(const ulonglong2*)&ws[k][2 * cx + 1];  // pairs 2,3
        u64 hp[4];
        #pragma unroll
        for (int i = 0; i < 4; i++) hp[i] = pack2(hs[ny * 4 + i][k]);
        #pragma unroll
        for (int i = 0; i < 4; i++) {
            ffma2(acc[i][0], hp[i], wa.x);
            ffma2(acc[i][1], hp[i], wa.y);
            ffma2(acc[i][2], hp[i], wb.x);
            ffma2(acc[i][3], hp[i], wb.y);
        }
    }

    // --- store feat / resval (u64 pairs preserve float order) ---
    #pragma unroll
    for (int i = 0; i < 4; i++) {
        int node = base + ny * 4 + i;
        if (node >= N_NODES) break;
        float* dstp = (cx < 8) ? &g_feat[node * 64 + cx * 8]
                               : &out[node * 64 + (cx - 8) * 8];
        ulonglong2 v0 = make_ulonglong2(acc[i][0], acc[i][1]);
        ulonglong2 v1 = make_ulonglong2(acc[i][2], acc[i][3]);
        *(ulonglong2*)&dstp[0] = v0;
        *(ulonglong2*)&dstp[4] = v1;
    }

    // --- fused el/er epilogue ---
    // Feat-side threads (cx<8): thread's 8 cols are the (cx&1)-th half of
    // head (cx>>1); partner lane (lane xor 1) holds the other half of the
    // same head & same nodes. ALL lanes execute the dots + shuffles so the
    // full-warp shuffle mask is valid; cx>=8 lanes compute throwaway values
    // (attn indexed via cx&7 to stay in bounds).
    {
        int c8 = cx & 7;
        const ulonglong2* al4 = (const ulonglong2*)attn_l;  // 4 floats per ull2
        const ulonglong2* ar4 = (const ulonglong2*)attn_r;
        ulonglong2 ala = al4[2 * c8], alb = al4[2 * c8 + 1];
        ulonglong2 ara = ar4[2 * c8], arb = ar4[2 * c8 + 1];
        int head = c8 >> 1;
        #pragma unroll
        for (int i = 0; i < 4; i++) {
            u64 dl = 0ull, dr = 0ull;
            ffma2(dl, acc[i][0], ala.x); ffma2(dl, acc[i][1], ala.y);
            ffma2(dl, acc[i][2], alb.x); ffma2(dl, acc[i][3], alb.y);
            ffma2(dr, acc[i][0], ara.x); ffma2(dr, acc[i][1], ara.y);
            ffma2(dr, acc[i][2], arb.x); ffma2(dr, acc[i][3], arb.y);
            float pl = unpack_sum(dl);
            float pr = unpack_sum(dr);
            pl += __shfl_xor_sync(0xffffffffu, pl, 1);
            pr += __shfl_xor_sync(0xffffffffu, pr, 1);
            int node = base + ny * 4 + i;
            if (cx < 8 && (cx & 1) == 0 && node < N_NODES) {
                g_el[node * 4 + head] = pl;
                g_er[node * 4 + head] = pr;
            }
        }
    }
}

// ---------------------------------------------------------------------------
// Edge scatter with fused leaky-relu + head-softmax (unchanged from R3).
// 16 lanes per edge; lane j owns head (j&3), dim group (j>>2).
// One expf per lane; 4-lane butterfly for max+sum; red.global.add.v4.f32.
// ---------------------------------------------------------------------------
__global__ void __launch_bounds__(256) scatter_kernel(
    const void* __restrict__ src,
    const void* __restrict__ dst,
    float* __restrict__ out)
{
    int t = blockIdx.x * 256 + threadIdx.x;
    int e = t >> 4;
    if (e >= N_EDGES) return;
    int j  = t & 15;
    int hh = j & 3;
    int g  = j >> 2;

    int is64 = g_idx64;
    int s = ld_idx(src, e, is64);
    int d = ld_idx(dst, e, is64);

    float ev = g_el[s * 4 + hh] + g_er[d * 4 + hh];
    ev = (ev > 0.f) ? ev : NEG_SLOPE * ev;

    float m = ev;
    m = fmaxf(m, __shfl_xor_sync(0xffffffffu, m, 1));
    m = fmaxf(m, __shfl_xor_sync(0xffffffffu, m, 2));
    float x = __expf(ev - m);
    float ssum = x;
    ssum += __shfl_xor_sync(0xffffffffu, ssum, 1);
    ssum += __shfl_xor_sync(0xffffffffu, ssum, 2);
    float a = __fdividef(x, ssum);

    int col = hh * 16 + g * 4;
    float4 f = *(const float4*)&g_feat[s * 64 + col];
    float4 v = make_float4(f.x * a, f.y * a, f.z * a, f.w * a);

    float* addr = out + (long long)d * 64 + col;
    asm volatile("red.global.add.v4.f32 [%0], {%1,%2,%3,%4};"
                 :: "l"(addr), "f"(v.x), "f"(v.y), "f"(v.z), "f"(v.w)
                 : "memory");
}

// ---------------------------------------------------------------------------
extern "C" void kernel_launch(void* const* d_in, const int* in_sizes, int n_in,
                              void* d_out, int out_size) {
    const float* h    = (const float*)d_in[0];
    const void*  src  = d_in[1];
    const void*  dst  = d_in[2];
    const float* Wfc  = (const float*)d_in[3];
    const float* al   = (const float*)d_in[4];
    const float* ar   = (const float*)d_in[5];
    const float* Wres = (const float*)d_in[6];
    float* out = (float*)d_out;

    int fc_blocks = (N_NODES + 63) / 64;                 // 782
    fc_kernel<<<fc_blocks, 256>>>(h, Wfc, Wres, al, ar, (const int*)src, out);

    long long threads = (long long)N_EDGES * 16;
    int sc_blocks = (int)((threads + 255) / 256);
    scatter_kernel<<<sc_blocks, 256>>>(src, dst, out);
}